// round 2
// baseline (speedup 1.0000x reference)
#include <cuda_runtime.h>
#include <cuda_bf16.h>
#include <math.h>

// Problem constants
#define BB   4
#define NN   2048
#define CC1  512
#define CC2  128
#define HH   8
#define CATD 640      // C1 + C2
#define DHH  80       // per-head dim (64 color + 16 depth)
#define MR   (BB*NN)  // 8192 token rows

// ---------------------------------------------------------------------------
// Scratch (device globals; no dynamic allocation allowed)
// ---------------------------------------------------------------------------
__device__ __align__(16) float g_cat[MR*CATD];  // concat(color, depth)
__device__ __align__(16) float g_qt [MR*CATD];  // q = cat @ Wq + bq  (token-major, [m, h*80+d])
__device__ __align__(16) float g_kt [MR*CATD];  // k
__device__ __align__(16) float g_cvt[MR*CC1];   // color values
__device__ __align__(16) float g_dvt[MR*CC2];   // depth values
__device__ __align__(16) float g_oc [MR*CC1];   // attn output (color part, [m, h*64+d])
__device__ __align__(16) float g_od [MR*CC2];   // attn output (depth part, [m, h*16+d])

// ---------------------------------------------------------------------------
// Concat kernel: g_cat[m, 0:512] = color, g_cat[m, 512:640] = depth
// ---------------------------------------------------------------------------
__global__ void concat_kernel(const float* __restrict__ color,
                              const float* __restrict__ depth) {
    int idx = blockIdx.x * 256 + threadIdx.x;
    if (idx >= MR * CATD) return;
    int m = idx / CATD;
    int c = idx - m * CATD;
    g_cat[idx] = (c < CC1) ? color[m * CC1 + c] : depth[m * CC2 + (c - CC1)];
}

// ---------------------------------------------------------------------------
// Tiled fp32 GEMM with bias: Y[M,Nout] = X[M,K] @ W[K,Nout] + bias
// 64x64 block tile, K-step 32, 256 threads, 4x4 per-thread microtile.
// Requires M%64==0, K%32==0, Nout%64==0 (holds for all uses here).
// ---------------------------------------------------------------------------
__global__ void __launch_bounds__(256) gemm_bias(
    const float* __restrict__ X, const float* __restrict__ W,
    const float* __restrict__ bias, float* __restrict__ Y,
    int M, int K, int Nout)
{
    __shared__ float As[32][65];   // [k][m], padded: conflict-free transpose store
    __shared__ __align__(16) float Bs[32][64];   // [k][n]

    const int bm  = blockIdx.y * 64;
    const int bn  = blockIdx.x * 64;
    const int tid = threadIdx.x;
    const int tx  = tid & 15;      // 0..15 -> col group
    const int ty  = tid >> 4;      // 0..15 -> row group

    float acc[4][4];
#pragma unroll
    for (int i = 0; i < 4; i++)
#pragma unroll
        for (int j = 0; j < 4; j++) acc[i][j] = 0.f;

    for (int k0 = 0; k0 < K; k0 += 32) {
        // Load A tile 64(m) x 32(k), coalesced on k, transposed into As[k][m]
#pragma unroll
        for (int r = 0; r < 8; r++) {
            int m  = (tid >> 5) + r * 8;
            int kk = tid & 31;
            As[kk][m] = X[(bm + m) * K + k0 + kk];
        }
        // Load B tile 32(k) x 64(n), coalesced on n
#pragma unroll
        for (int r = 0; r < 8; r++) {
            int kk = (tid >> 6) + r * 4;
            int n  = tid & 63;
            Bs[kk][n] = W[(k0 + kk) * Nout + bn + n];
        }
        __syncthreads();

#pragma unroll
        for (int kk = 0; kk < 32; kk++) {
            float4 b4 = *reinterpret_cast<const float4*>(&Bs[kk][tx * 4]);
            float a0 = As[kk][ty * 4 + 0];
            float a1 = As[kk][ty * 4 + 1];
            float a2 = As[kk][ty * 4 + 2];
            float a3 = As[kk][ty * 4 + 3];
            acc[0][0] += a0 * b4.x; acc[0][1] += a0 * b4.y; acc[0][2] += a0 * b4.z; acc[0][3] += a0 * b4.w;
            acc[1][0] += a1 * b4.x; acc[1][1] += a1 * b4.y; acc[1][2] += a1 * b4.z; acc[1][3] += a1 * b4.w;
            acc[2][0] += a2 * b4.x; acc[2][1] += a2 * b4.y; acc[2][2] += a2 * b4.z; acc[2][3] += a2 * b4.w;
            acc[3][0] += a3 * b4.x; acc[3][1] += a3 * b4.y; acc[3][2] += a3 * b4.z; acc[3][3] += a3 * b4.w;
        }
        __syncthreads();
    }

    const float bj0 = bias[bn + tx * 4 + 0];
    const float bj1 = bias[bn + tx * 4 + 1];
    const float bj2 = bias[bn + tx * 4 + 2];
    const float bj3 = bias[bn + tx * 4 + 3];
#pragma unroll
    for (int i = 0; i < 4; i++) {
        float4 o;
        o.x = acc[i][0] + bj0;
        o.y = acc[i][1] + bj1;
        o.z = acc[i][2] + bj2;
        o.w = acc[i][3] + bj3;
        *reinterpret_cast<float4*>(&Y[(bm + ty * 4 + i) * Nout + bn + tx * 4]) = o;
    }
}

// ---------------------------------------------------------------------------
// Flash attention per (b,h): grid (N/64, B*H), 256 threads.
// 64 q-rows per block; 4 threads per row, each owning a 20-wide slice of dh=80.
// Online softmax in 16-column chunks (keeps register count ~80).
// Reads q/k from token-major projection buffers (strided, head slice).
// V = [cv(64) | dv(16)] gathered on load. Output scattered to g_oc/g_od.
// ---------------------------------------------------------------------------
__global__ void __launch_bounds__(256) attn_kernel() {
    __shared__ __align__(16) float Ks[64][DHH];
    __shared__ __align__(16) float Vs[64][DHH];

    const int bh = blockIdx.y;
    const int b  = bh >> 3;
    const int h  = bh & 7;
    const int q0 = blockIdx.x * 64;
    const int tid = threadIdx.x;
    const int r = tid >> 2;   // 0..63: q-row within block
    const int t = tid & 3;    // 0..3 : dh slice owner
    const float scale = 0.11180339887498948f;  // 1/sqrt(80)

    // Q slice in registers
    float q[20];
    {
        const float* qrow = g_qt + (b * NN + q0 + r) * CATD + h * DHH + t * 20;
#pragma unroll
        for (int j = 0; j < 20; j += 4) {
            float4 v = *reinterpret_cast<const float4*>(qrow + j);
            q[j] = v.x; q[j + 1] = v.y; q[j + 2] = v.z; q[j + 3] = v.w;
        }
    }
    float o[20];
#pragma unroll
    for (int j = 0; j < 20; j++) o[j] = 0.f;
    float mi = -3.0e38f, li = 0.f;

    for (int kt = 0; kt < NN / 64; kt++) {
        const int k0 = kt * 64;
        // Load K and V tiles (V gathers cv|dv)
        for (int i = tid; i < 64 * DHH; i += 256) {
            int rr = i / DHH;
            int c  = i - rr * DHH;
            int tok = b * NN + k0 + rr;
            Ks[rr][c] = g_kt[tok * CATD + h * DHH + c];
            Vs[rr][c] = (c < 64) ? g_cvt[tok * CC1 + h * 64 + c]
                                 : g_dvt[tok * CC2 + h * 16 + (c - 64)];
        }
        __syncthreads();

#pragma unroll
        for (int cc = 0; cc < 4; cc++) {
            // Partial scores for 16 columns over this thread's 20-dim slice
            float s[16];
#pragma unroll
            for (int c = 0; c < 16; c++) {
                const float* kr = &Ks[cc * 16 + c][t * 20];
                float p = 0.f;
#pragma unroll
                for (int j = 0; j < 20; j += 4) {
                    float4 kv = *reinterpret_cast<const float4*>(kr + j);
                    p += q[j] * kv.x + q[j + 1] * kv.y + q[j + 2] * kv.z + q[j + 3] * kv.w;
                }
                s[c] = p;
            }
            // Reduce across the 4 slice-owners of this row (lanes r*4+t contiguous)
#pragma unroll
            for (int c = 0; c < 16; c++) {
                s[c] += __shfl_xor_sync(0xffffffffu, s[c], 1);
                s[c] += __shfl_xor_sync(0xffffffffu, s[c], 2);
                s[c] *= scale;
            }
            // Online softmax update (chunk of 16)
            float mnew = mi;
#pragma unroll
            for (int c = 0; c < 16; c++) mnew = fmaxf(mnew, s[c]);
            float alpha = __expf(mi - mnew);
            float lsum = 0.f;
#pragma unroll
            for (int c = 0; c < 16; c++) { s[c] = __expf(s[c] - mnew); lsum += s[c]; }
            li = li * alpha + lsum;
#pragma unroll
            for (int j = 0; j < 20; j++) o[j] *= alpha;
#pragma unroll
            for (int c = 0; c < 16; c++) {
                const float* vr = &Vs[cc * 16 + c][t * 20];
                float pc = s[c];
#pragma unroll
                for (int j = 0; j < 20; j += 4) {
                    float4 vv = *reinterpret_cast<const float4*>(vr + j);
                    o[j]     += pc * vv.x;
                    o[j + 1] += pc * vv.y;
                    o[j + 2] += pc * vv.z;
                    o[j + 3] += pc * vv.w;
                }
            }
            mi = mnew;
        }
        __syncthreads();
    }

    const float inv = 1.f / li;
    const int row = b * NN + q0 + r;
#pragma unroll
    for (int j = 0; j < 20; j++) {
        float val = o[j] * inv;
        int c = t * 20 + j;
        if (c < 64) g_oc[row * CC1 + h * 64 + c] = val;
        else        g_od[row * CC2 + h * 16 + (c - 64)] = val;
    }
}

// ---------------------------------------------------------------------------
// kernel_launch
// ---------------------------------------------------------------------------
extern "C" void kernel_launch(void* const* d_in, const int* in_sizes, int n_in,
                              void* d_out, int out_size) {
    (void)in_sizes; (void)n_in; (void)out_size;
    const float* color = (const float*)d_in[0];
    const float* depth = (const float*)d_in[1];
    const float* Wq  = (const float*)d_in[2];
    const float* bq  = (const float*)d_in[3];
    const float* Wk  = (const float*)d_in[4];
    const float* bk  = (const float*)d_in[5];
    const float* Wcv = (const float*)d_in[6];
    const float* bcv = (const float*)d_in[7];
    const float* Wdv = (const float*)d_in[8];
    const float* bdv = (const float*)d_in[9];
    const float* Wcl = (const float*)d_in[10];
    const float* bcl = (const float*)d_in[11];
    const float* Wdl = (const float*)d_in[12];
    const float* bdl = (const float*)d_in[13];

    float* out       = (float*)d_out;
    float* color_out = out;                       // [4,2048,512]
    float* depth_out = out + (size_t)MR * CC1;    // [4,2048,128]

    float *cat_p, *qt_p, *kt_p, *cvt_p, *dvt_p, *oc_p, *od_p;
    cudaGetSymbolAddress((void**)&cat_p, g_cat);
    cudaGetSymbolAddress((void**)&qt_p,  g_qt);
    cudaGetSymbolAddress((void**)&kt_p,  g_kt);
    cudaGetSymbolAddress((void**)&cvt_p, g_cvt);
    cudaGetSymbolAddress((void**)&dvt_p, g_dvt);
    cudaGetSymbolAddress((void**)&oc_p,  g_oc);
    cudaGetSymbolAddress((void**)&od_p,  g_od);

    // 1. concat
    concat_kernel<<<(MR * CATD + 255) / 256, 256>>>(color, depth);

    // 2. projections
    gemm_bias<<<dim3(CATD / 64, MR / 64), 256>>>(cat_p, Wq,  bq,  qt_p,  MR, CATD, CATD);
    gemm_bias<<<dim3(CATD / 64, MR / 64), 256>>>(cat_p, Wk,  bk,  kt_p,  MR, CATD, CATD);
    gemm_bias<<<dim3(CC1 / 64,  MR / 64), 256>>>(color, Wcv, bcv, cvt_p, MR, CC1,  CC1);
    gemm_bias<<<dim3(CC2 / 64,  MR / 64), 256>>>(depth, Wdv, bdv, dvt_p, MR, CC2,  CC2);

    // 3. attention (flash-style, fused color/depth values)
    attn_kernel<<<dim3(NN / 64, BB * HH), 256>>>();

    // 4. output projections straight into d_out
    gemm_bias<<<dim3(CC1 / 64, MR / 64), 256>>>(oc_p, Wcl, bcl, color_out, MR, CC1, CC1);
    gemm_bias<<<dim3(CC2 / 64, MR / 64), 256>>>(od_p, Wdl, bdl, depth_out, MR, CC2, CC2);
}

// round 3
// speedup vs baseline: 1.0028x; 1.0028x over previous
#include <cuda_runtime.h>
#include <cuda_bf16.h>
#include <math.h>

// Problem constants
#define BB   4
#define NN   2048
#define CC1  512
#define CC2  128
#define HH   8
#define CATD 640      // C1 + C2
#define DHH  80       // per-head dim (64 color + 16 depth)
#define MR   (BB*NN)  // 8192 token rows

// ---------------------------------------------------------------------------
// Scratch (device globals; no dynamic allocation allowed)
// ---------------------------------------------------------------------------
__device__ __align__(16) float g_cat[MR*CATD];  // concat(color, depth)
__device__ __align__(16) float g_qt [MR*CATD];  // q = cat @ Wq + bq  (token-major, [m, h*80+d])
__device__ __align__(16) float g_kt [MR*CATD];  // k
__device__ __align__(16) float g_cvt[MR*CC1];   // color values
__device__ __align__(16) float g_dvt[MR*CC2];   // depth values
__device__ __align__(16) float g_oc [MR*CC1];   // attn output (color part, [m, h*64+d])
__device__ __align__(16) float g_od [MR*CC2];   // attn output (depth part, [m, h*16+d])

// ---------------------------------------------------------------------------
// Concat kernel: g_cat[m, 0:512] = color, g_cat[m, 512:640] = depth
// ---------------------------------------------------------------------------
__global__ void concat_kernel(const float* __restrict__ color,
                              const float* __restrict__ depth) {
    int idx = blockIdx.x * 256 + threadIdx.x;
    if (idx >= MR * CATD) return;
    int m = idx / CATD;
    int c = idx - m * CATD;
    g_cat[idx] = (c < CC1) ? color[m * CC1 + c] : depth[m * CC2 + (c - CC1)];
}

// ---------------------------------------------------------------------------
// Tiled fp32 GEMM with bias: Y[M,Nout] = X[M,K] @ W[K,Nout] + bias
// 64x64 block tile, K-step 32, 256 threads, 4x4 per-thread microtile.
// Requires M%64==0, K%32==0, Nout%64==0 (holds for all uses here).
// ---------------------------------------------------------------------------
__global__ void __launch_bounds__(256) gemm_bias(
    const float* __restrict__ X, const float* __restrict__ W,
    const float* __restrict__ bias, float* __restrict__ Y,
    int M, int K, int Nout)
{
    __shared__ float As[32][65];   // [k][m], padded: conflict-free transpose store
    __shared__ __align__(16) float Bs[32][64];   // [k][n]

    const int bm  = blockIdx.y * 64;
    const int bn  = blockIdx.x * 64;
    const int tid = threadIdx.x;
    const int tx  = tid & 15;      // 0..15 -> col group
    const int ty  = tid >> 4;      // 0..15 -> row group

    float acc[4][4];
#pragma unroll
    for (int i = 0; i < 4; i++)
#pragma unroll
        for (int j = 0; j < 4; j++) acc[i][j] = 0.f;

    for (int k0 = 0; k0 < K; k0 += 32) {
        // Load A tile 64(m) x 32(k), coalesced on k, transposed into As[k][m]
#pragma unroll
        for (int r = 0; r < 8; r++) {
            int m  = (tid >> 5) + r * 8;
            int kk = tid & 31;
            As[kk][m] = X[(bm + m) * K + k0 + kk];
        }
        // Load B tile 32(k) x 64(n), coalesced on n
#pragma unroll
        for (int r = 0; r < 8; r++) {
            int kk = (tid >> 6) + r * 4;
            int n  = tid & 63;
            Bs[kk][n] = W[(k0 + kk) * Nout + bn + n];
        }
        __syncthreads();

#pragma unroll
        for (int kk = 0; kk < 32; kk++) {
            float4 b4 = *reinterpret_cast<const float4*>(&Bs[kk][tx * 4]);
            float a0 = As[kk][ty * 4 + 0];
            float a1 = As[kk][ty * 4 + 1];
            float a2 = As[kk][ty * 4 + 2];
            float a3 = As[kk][ty * 4 + 3];
            acc[0][0] += a0 * b4.x; acc[0][1] += a0 * b4.y; acc[0][2] += a0 * b4.z; acc[0][3] += a0 * b4.w;
            acc[1][0] += a1 * b4.x; acc[1][1] += a1 * b4.y; acc[1][2] += a1 * b4.z; acc[1][3] += a1 * b4.w;
            acc[2][0] += a2 * b4.x; acc[2][1] += a2 * b4.y; acc[2][2] += a2 * b4.z; acc[2][3] += a2 * b4.w;
            acc[3][0] += a3 * b4.x; acc[3][1] += a3 * b4.y; acc[3][2] += a3 * b4.z; acc[3][3] += a3 * b4.w;
        }
        __syncthreads();
    }

    const float bj0 = bias[bn + tx * 4 + 0];
    const float bj1 = bias[bn + tx * 4 + 1];
    const float bj2 = bias[bn + tx * 4 + 2];
    const float bj3 = bias[bn + tx * 4 + 3];
#pragma unroll
    for (int i = 0; i < 4; i++) {
        float4 o;
        o.x = acc[i][0] + bj0;
        o.y = acc[i][1] + bj1;
        o.z = acc[i][2] + bj2;
        o.w = acc[i][3] + bj3;
        *reinterpret_cast<float4*>(&Y[(bm + ty * 4 + i) * Nout + bn + tx * 4]) = o;
    }
}

// ---------------------------------------------------------------------------
// Flash attention per (b,h): grid (N/64, B*H), 256 threads.
// 64 q-rows per block; 4 threads per row, each owning a 20-wide slice of dh=80.
// Online softmax in 16-column chunks (keeps register count ~80).
// Reads q/k from token-major projection buffers (strided, head slice).
// V = [cv(64) | dv(16)] gathered on load. Output scattered to g_oc/g_od.
// ---------------------------------------------------------------------------
__global__ void __launch_bounds__(256) attn_kernel() {
    __shared__ __align__(16) float Ks[64][DHH];
    __shared__ __align__(16) float Vs[64][DHH];

    const int bh = blockIdx.y;
    const int b  = bh >> 3;
    const int h  = bh & 7;
    const int q0 = blockIdx.x * 64;
    const int tid = threadIdx.x;
    const int r = tid >> 2;   // 0..63: q-row within block
    const int t = tid & 3;    // 0..3 : dh slice owner
    const float scale = 0.11180339887498948f;  // 1/sqrt(80)

    // Q slice in registers
    float q[20];
    {
        const float* qrow = g_qt + (b * NN + q0 + r) * CATD + h * DHH + t * 20;
#pragma unroll
        for (int j = 0; j < 20; j += 4) {
            float4 v = *reinterpret_cast<const float4*>(qrow + j);
            q[j] = v.x; q[j + 1] = v.y; q[j + 2] = v.z; q[j + 3] = v.w;
        }
    }
    float o[20];
#pragma unroll
    for (int j = 0; j < 20; j++) o[j] = 0.f;
    float mi = -3.0e38f, li = 0.f;

    for (int kt = 0; kt < NN / 64; kt++) {
        const int k0 = kt * 64;
        // Load K and V tiles (V gathers cv|dv)
        for (int i = tid; i < 64 * DHH; i += 256) {
            int rr = i / DHH;
            int c  = i - rr * DHH;
            int tok = b * NN + k0 + rr;
            Ks[rr][c] = g_kt[tok * CATD + h * DHH + c];
            Vs[rr][c] = (c < 64) ? g_cvt[tok * CC1 + h * 64 + c]
                                 : g_dvt[tok * CC2 + h * 16 + (c - 64)];
        }
        __syncthreads();

#pragma unroll
        for (int cc = 0; cc < 4; cc++) {
            // Partial scores for 16 columns over this thread's 20-dim slice
            float s[16];
#pragma unroll
            for (int c = 0; c < 16; c++) {
                const float* kr = &Ks[cc * 16 + c][t * 20];
                float p = 0.f;
#pragma unroll
                for (int j = 0; j < 20; j += 4) {
                    float4 kv = *reinterpret_cast<const float4*>(kr + j);
                    p += q[j] * kv.x + q[j + 1] * kv.y + q[j + 2] * kv.z + q[j + 3] * kv.w;
                }
                s[c] = p;
            }
            // Reduce across the 4 slice-owners of this row (lanes r*4+t contiguous)
#pragma unroll
            for (int c = 0; c < 16; c++) {
                s[c] += __shfl_xor_sync(0xffffffffu, s[c], 1);
                s[c] += __shfl_xor_sync(0xffffffffu, s[c], 2);
                s[c] *= scale;
            }
            // Online softmax update (chunk of 16)
            float mnew = mi;
#pragma unroll
            for (int c = 0; c < 16; c++) mnew = fmaxf(mnew, s[c]);
            float alpha = __expf(mi - mnew);
            float lsum = 0.f;
#pragma unroll
            for (int c = 0; c < 16; c++) { s[c] = __expf(s[c] - mnew); lsum += s[c]; }
            li = li * alpha + lsum;
#pragma unroll
            for (int j = 0; j < 20; j++) o[j] *= alpha;
#pragma unroll
            for (int c = 0; c < 16; c++) {
                const float* vr = &Vs[cc * 16 + c][t * 20];
                float pc = s[c];
#pragma unroll
                for (int j = 0; j < 20; j += 4) {
                    float4 vv = *reinterpret_cast<const float4*>(vr + j);
                    o[j]     += pc * vv.x;
                    o[j + 1] += pc * vv.y;
                    o[j + 2] += pc * vv.z;
                    o[j + 3] += pc * vv.w;
                }
            }
            mi = mnew;
        }
        __syncthreads();
    }

    const float inv = 1.f / li;
    const int row = b * NN + q0 + r;
#pragma unroll
    for (int j = 0; j < 20; j++) {
        float val = o[j] * inv;
        int c = t * 20 + j;
        if (c < 64) g_oc[row * CC1 + h * 64 + c] = val;
        else        g_od[row * CC2 + h * 16 + (c - 64)] = val;
    }
}

// ---------------------------------------------------------------------------
// kernel_launch
// ---------------------------------------------------------------------------
extern "C" void kernel_launch(void* const* d_in, const int* in_sizes, int n_in,
                              void* d_out, int out_size) {
    (void)in_sizes; (void)n_in; (void)out_size;
    const float* color = (const float*)d_in[0];
    const float* depth = (const float*)d_in[1];
    const float* Wq  = (const float*)d_in[2];
    const float* bq  = (const float*)d_in[3];
    const float* Wk  = (const float*)d_in[4];
    const float* bk  = (const float*)d_in[5];
    const float* Wcv = (const float*)d_in[6];
    const float* bcv = (const float*)d_in[7];
    const float* Wdv = (const float*)d_in[8];
    const float* bdv = (const float*)d_in[9];
    const float* Wcl = (const float*)d_in[10];
    const float* bcl = (const float*)d_in[11];
    const float* Wdl = (const float*)d_in[12];
    const float* bdl = (const float*)d_in[13];

    float* out       = (float*)d_out;
    float* color_out = out;                       // [4,2048,512]
    float* depth_out = out + (size_t)MR * CC1;    // [4,2048,128]

    float *cat_p, *qt_p, *kt_p, *cvt_p, *dvt_p, *oc_p, *od_p;
    cudaGetSymbolAddress((void**)&cat_p, g_cat);
    cudaGetSymbolAddress((void**)&qt_p,  g_qt);
    cudaGetSymbolAddress((void**)&kt_p,  g_kt);
    cudaGetSymbolAddress((void**)&cvt_p, g_cvt);
    cudaGetSymbolAddress((void**)&dvt_p, g_dvt);
    cudaGetSymbolAddress((void**)&oc_p,  g_oc);
    cudaGetSymbolAddress((void**)&od_p,  g_od);

    // 1. concat
    concat_kernel<<<(MR * CATD + 255) / 256, 256>>>(color, depth);

    // 2. projections
    gemm_bias<<<dim3(CATD / 64, MR / 64), 256>>>(cat_p, Wq,  bq,  qt_p,  MR, CATD, CATD);
    gemm_bias<<<dim3(CATD / 64, MR / 64), 256>>>(cat_p, Wk,  bk,  kt_p,  MR, CATD, CATD);
    gemm_bias<<<dim3(CC1 / 64,  MR / 64), 256>>>(color, Wcv, bcv, cvt_p, MR, CC1,  CC1);
    gemm_bias<<<dim3(CC2 / 64,  MR / 64), 256>>>(depth, Wdv, bdv, dvt_p, MR, CC2,  CC2);

    // 3. attention (flash-style, fused color/depth values)
    attn_kernel<<<dim3(NN / 64, BB * HH), 256>>>();

    // 4. output projections straight into d_out
    gemm_bias<<<dim3(CC1 / 64, MR / 64), 256>>>(oc_p, Wcl, bcl, color_out, MR, CC1, CC1);
    gemm_bias<<<dim3(CC2 / 64, MR / 64), 256>>>(od_p, Wdl, bdl, depth_out, MR, CC2, CC2);
}

// round 4
// speedup vs baseline: 1.0035x; 1.0007x over previous
#include <cuda_runtime.h>
#include <cuda_bf16.h>
#include <math.h>

// Problem constants
#define BB   4
#define NN   2048
#define CC1  512
#define CC2  128
#define HH   8
#define CATD 640      // C1 + C2
#define DHH  80       // per-head dim (64 color + 16 depth)
#define MR   (BB*NN)  // 8192 token rows

// ---------------------------------------------------------------------------
// Scratch (device globals; no dynamic allocation allowed)
// ---------------------------------------------------------------------------
__device__ __align__(16) float g_cat[MR*CATD];  // concat(color, depth)
__device__ __align__(16) float g_qt [MR*CATD];  // q = cat @ Wq + bq  (token-major, [m, h*80+d])
__device__ __align__(16) float g_kt [MR*CATD];  // k
__device__ __align__(16) float g_cvt[MR*CC1];   // color values
__device__ __align__(16) float g_dvt[MR*CC2];   // depth values
__device__ __align__(16) float g_oc [MR*CC1];   // attn output (color part, [m, h*64+d])
__device__ __align__(16) float g_od [MR*CC2];   // attn output (depth part, [m, h*16+d])

// ---------------------------------------------------------------------------
// Concat kernel: g_cat[m, 0:512] = color, g_cat[m, 512:640] = depth
// ---------------------------------------------------------------------------
__global__ void concat_kernel(const float* __restrict__ color,
                              const float* __restrict__ depth) {
    int idx = blockIdx.x * 256 + threadIdx.x;
    if (idx >= MR * CATD) return;
    int m = idx / CATD;
    int c = idx - m * CATD;
    g_cat[idx] = (c < CC1) ? color[m * CC1 + c] : depth[m * CC2 + (c - CC1)];
}

// ---------------------------------------------------------------------------
// Tiled fp32 GEMM with bias: Y[M,Nout] = X[M,K] @ W[K,Nout] + bias
// 64x64 block tile, K-step 32, 256 threads, 4x4 per-thread microtile.
// Requires M%64==0, K%32==0, Nout%64==0 (holds for all uses here).
// ---------------------------------------------------------------------------
__global__ void __launch_bounds__(256) gemm_bias(
    const float* __restrict__ X, const float* __restrict__ W,
    const float* __restrict__ bias, float* __restrict__ Y,
    int M, int K, int Nout)
{
    __shared__ float As[32][65];   // [k][m], padded: conflict-free transpose store
    __shared__ __align__(16) float Bs[32][64];   // [k][n]

    const int bm  = blockIdx.y * 64;
    const int bn  = blockIdx.x * 64;
    const int tid = threadIdx.x;
    const int tx  = tid & 15;      // 0..15 -> col group
    const int ty  = tid >> 4;      // 0..15 -> row group

    float acc[4][4];
#pragma unroll
    for (int i = 0; i < 4; i++)
#pragma unroll
        for (int j = 0; j < 4; j++) acc[i][j] = 0.f;

    for (int k0 = 0; k0 < K; k0 += 32) {
        // Load A tile 64(m) x 32(k), coalesced on k, transposed into As[k][m]
#pragma unroll
        for (int r = 0; r < 8; r++) {
            int m  = (tid >> 5) + r * 8;
            int kk = tid & 31;
            As[kk][m] = X[(bm + m) * K + k0 + kk];
        }
        // Load B tile 32(k) x 64(n), coalesced on n
#pragma unroll
        for (int r = 0; r < 8; r++) {
            int kk = (tid >> 6) + r * 4;
            int n  = tid & 63;
            Bs[kk][n] = W[(k0 + kk) * Nout + bn + n];
        }
        __syncthreads();

#pragma unroll
        for (int kk = 0; kk < 32; kk++) {
            float4 b4 = *reinterpret_cast<const float4*>(&Bs[kk][tx * 4]);
            float a0 = As[kk][ty * 4 + 0];
            float a1 = As[kk][ty * 4 + 1];
            float a2 = As[kk][ty * 4 + 2];
            float a3 = As[kk][ty * 4 + 3];
            acc[0][0] += a0 * b4.x; acc[0][1] += a0 * b4.y; acc[0][2] += a0 * b4.z; acc[0][3] += a0 * b4.w;
            acc[1][0] += a1 * b4.x; acc[1][1] += a1 * b4.y; acc[1][2] += a1 * b4.z; acc[1][3] += a1 * b4.w;
            acc[2][0] += a2 * b4.x; acc[2][1] += a2 * b4.y; acc[2][2] += a2 * b4.z; acc[2][3] += a2 * b4.w;
            acc[3][0] += a3 * b4.x; acc[3][1] += a3 * b4.y; acc[3][2] += a3 * b4.z; acc[3][3] += a3 * b4.w;
        }
        __syncthreads();
    }

    const float bj0 = bias[bn + tx * 4 + 0];
    const float bj1 = bias[bn + tx * 4 + 1];
    const float bj2 = bias[bn + tx * 4 + 2];
    const float bj3 = bias[bn + tx * 4 + 3];
#pragma unroll
    for (int i = 0; i < 4; i++) {
        float4 o;
        o.x = acc[i][0] + bj0;
        o.y = acc[i][1] + bj1;
        o.z = acc[i][2] + bj2;
        o.w = acc[i][3] + bj3;
        *reinterpret_cast<float4*>(&Y[(bm + ty * 4 + i) * Nout + bn + tx * 4]) = o;
    }
}

// ---------------------------------------------------------------------------
// Flash attention per (b,h): grid (N/64, B*H), 256 threads.
// 64 q-rows per block; 4 threads per row, each owning a 20-wide slice of dh=80.
// Online softmax in 16-column chunks (keeps register count ~80).
// Reads q/k from token-major projection buffers (strided, head slice).
// V = [cv(64) | dv(16)] gathered on load. Output scattered to g_oc/g_od.
// ---------------------------------------------------------------------------
__global__ void __launch_bounds__(256) attn_kernel() {
    __shared__ __align__(16) float Ks[64][DHH];
    __shared__ __align__(16) float Vs[64][DHH];

    const int bh = blockIdx.y;
    const int b  = bh >> 3;
    const int h  = bh & 7;
    const int q0 = blockIdx.x * 64;
    const int tid = threadIdx.x;
    const int r = tid >> 2;   // 0..63: q-row within block
    const int t = tid & 3;    // 0..3 : dh slice owner
    const float scale = 0.11180339887498948f;  // 1/sqrt(80)

    // Q slice in registers
    float q[20];
    {
        const float* qrow = g_qt + (b * NN + q0 + r) * CATD + h * DHH + t * 20;
#pragma unroll
        for (int j = 0; j < 20; j += 4) {
            float4 v = *reinterpret_cast<const float4*>(qrow + j);
            q[j] = v.x; q[j + 1] = v.y; q[j + 2] = v.z; q[j + 3] = v.w;
        }
    }
    float o[20];
#pragma unroll
    for (int j = 0; j < 20; j++) o[j] = 0.f;
    float mi = -3.0e38f, li = 0.f;

    for (int kt = 0; kt < NN / 64; kt++) {
        const int k0 = kt * 64;
        // Load K and V tiles (V gathers cv|dv)
        for (int i = tid; i < 64 * DHH; i += 256) {
            int rr = i / DHH;
            int c  = i - rr * DHH;
            int tok = b * NN + k0 + rr;
            Ks[rr][c] = g_kt[tok * CATD + h * DHH + c];
            Vs[rr][c] = (c < 64) ? g_cvt[tok * CC1 + h * 64 + c]
                                 : g_dvt[tok * CC2 + h * 16 + (c - 64)];
        }
        __syncthreads();

#pragma unroll
        for (int cc = 0; cc < 4; cc++) {
            // Partial scores for 16 columns over this thread's 20-dim slice
            float s[16];
#pragma unroll
            for (int c = 0; c < 16; c++) {
                const float* kr = &Ks[cc * 16 + c][t * 20];
                float p = 0.f;
#pragma unroll
                for (int j = 0; j < 20; j += 4) {
                    float4 kv = *reinterpret_cast<const float4*>(kr + j);
                    p += q[j] * kv.x + q[j + 1] * kv.y + q[j + 2] * kv.z + q[j + 3] * kv.w;
                }
                s[c] = p;
            }
            // Reduce across the 4 slice-owners of this row (lanes r*4+t contiguous)
#pragma unroll
            for (int c = 0; c < 16; c++) {
                s[c] += __shfl_xor_sync(0xffffffffu, s[c], 1);
                s[c] += __shfl_xor_sync(0xffffffffu, s[c], 2);
                s[c] *= scale;
            }
            // Online softmax update (chunk of 16)
            float mnew = mi;
#pragma unroll
            for (int c = 0; c < 16; c++) mnew = fmaxf(mnew, s[c]);
            float alpha = __expf(mi - mnew);
            float lsum = 0.f;
#pragma unroll
            for (int c = 0; c < 16; c++) { s[c] = __expf(s[c] - mnew); lsum += s[c]; }
            li = li * alpha + lsum;
#pragma unroll
            for (int j = 0; j < 20; j++) o[j] *= alpha;
#pragma unroll
            for (int c = 0; c < 16; c++) {
                const float* vr = &Vs[cc * 16 + c][t * 20];
                float pc = s[c];
#pragma unroll
                for (int j = 0; j < 20; j += 4) {
                    float4 vv = *reinterpret_cast<const float4*>(vr + j);
                    o[j]     += pc * vv.x;
                    o[j + 1] += pc * vv.y;
                    o[j + 2] += pc * vv.z;
                    o[j + 3] += pc * vv.w;
                }
            }
            mi = mnew;
        }
        __syncthreads();
    }

    const float inv = 1.f / li;
    const int row = b * NN + q0 + r;
#pragma unroll
    for (int j = 0; j < 20; j++) {
        float val = o[j] * inv;
        int c = t * 20 + j;
        if (c < 64) g_oc[row * CC1 + h * 64 + c] = val;
        else        g_od[row * CC2 + h * 16 + (c - 64)] = val;
    }
}

// ---------------------------------------------------------------------------
// kernel_launch
// ---------------------------------------------------------------------------
extern "C" void kernel_launch(void* const* d_in, const int* in_sizes, int n_in,
                              void* d_out, int out_size) {
    (void)in_sizes; (void)n_in; (void)out_size;
    const float* color = (const float*)d_in[0];
    const float* depth = (const float*)d_in[1];
    const float* Wq  = (const float*)d_in[2];
    const float* bq  = (const float*)d_in[3];
    const float* Wk  = (const float*)d_in[4];
    const float* bk  = (const float*)d_in[5];
    const float* Wcv = (const float*)d_in[6];
    const float* bcv = (const float*)d_in[7];
    const float* Wdv = (const float*)d_in[8];
    const float* bdv = (const float*)d_in[9];
    const float* Wcl = (const float*)d_in[10];
    const float* bcl = (const float*)d_in[11];
    const float* Wdl = (const float*)d_in[12];
    const float* bdl = (const float*)d_in[13];

    float* out       = (float*)d_out;
    float* color_out = out;                       // [4,2048,512]
    float* depth_out = out + (size_t)MR * CC1;    // [4,2048,128]

    float *cat_p, *qt_p, *kt_p, *cvt_p, *dvt_p, *oc_p, *od_p;
    cudaGetSymbolAddress((void**)&cat_p, g_cat);
    cudaGetSymbolAddress((void**)&qt_p,  g_qt);
    cudaGetSymbolAddress((void**)&kt_p,  g_kt);
    cudaGetSymbolAddress((void**)&cvt_p, g_cvt);
    cudaGetSymbolAddress((void**)&dvt_p, g_dvt);
    cudaGetSymbolAddress((void**)&oc_p,  g_oc);
    cudaGetSymbolAddress((void**)&od_p,  g_od);

    // 1. concat
    concat_kernel<<<(MR * CATD + 255) / 256, 256>>>(color, depth);

    // 2. projections
    gemm_bias<<<dim3(CATD / 64, MR / 64), 256>>>(cat_p, Wq,  bq,  qt_p,  MR, CATD, CATD);
    gemm_bias<<<dim3(CATD / 64, MR / 64), 256>>>(cat_p, Wk,  bk,  kt_p,  MR, CATD, CATD);
    gemm_bias<<<dim3(CC1 / 64,  MR / 64), 256>>>(color, Wcv, bcv, cvt_p, MR, CC1,  CC1);
    gemm_bias<<<dim3(CC2 / 64,  MR / 64), 256>>>(depth, Wdv, bdv, dvt_p, MR, CC2,  CC2);

    // 3. attention (flash-style, fused color/depth values)
    attn_kernel<<<dim3(NN / 64, BB * HH), 256>>>();

    // 4. output projections straight into d_out
    gemm_bias<<<dim3(CC1 / 64, MR / 64), 256>>>(oc_p, Wcl, bcl, color_out, MR, CC1, CC1);
    gemm_bias<<<dim3(CC2 / 64, MR / 64), 256>>>(od_p, Wdl, bdl, depth_out, MR, CC2, CC2);
}